// round 2
// baseline (speedup 1.0000x reference)
#include <cuda_runtime.h>
#include <cstdint>

// Problem constants (fixed by the reference)
#define H            8
#define NUM_DRAM     4096
#define NUM_HBM      819          // int(4096 * 0.2)
#define TOPK         256
#define PAGE_SIZE    16
#define HEAD_DIM     128
#define PAGE_ELEMS   4096         // 16 * 2 * 128
#define SEQ_PER_HEAD (NUM_HBM * PAGE_SIZE)              // 13104
#define KELEMS_HEAD  ((size_t)SEQ_PER_HEAD * HEAD_DIM)  // 1,677,312
#define KTOTAL       ((size_t)H * KELEMS_HEAD)          // 13,418,496

// Scratch: for each (head, hbm_slot), the DRAM page to pull in (-1 => keep hbm contents)
__device__ int g_src_page[H * NUM_HBM];

// ---------------------------------------------------------------------------
// Kernel 1: per-head LRU control. One block per head.
// Emulates the reference's JAX semantics exactly, including negative-index
// WRAPPING in scatters (idx=-1 -> NUM_HBM-1) before mode='drop' applies:
//   slot = d2h[topk]
//   pat[slot<0 ? 818 : slot] = step_f          (misses wrap to slot 818!)
//   order = stable_argsort(pat)
//   victim[miss_j] = order[excl_miss_count_j]
//   hbm scatter targets: miss -> victim ; hit -> 818 (wrapped -1), last wins
// ---------------------------------------------------------------------------
__global__ void lru_setup_kernel(const float* __restrict__ pat_g,
                                 const int*   __restrict__ d2h_g,
                                 const int*   __restrict__ topk_g,
                                 const int*   __restrict__ step_g)
{
    __shared__ float pat_s[NUM_HBM];
    __shared__ int   order_s[NUM_HBM];
    __shared__ int   topk_s[TOPK];
    __shared__ int   slot_s[TOPK];
    __shared__ int   rank_s[TOPK];
    __shared__ int   last_hit;

    const int h = blockIdx.x;
    const int t = threadIdx.x;
    const float step_f = (float)(step_g[0] + 1);

    if (t == 0) last_hit = -1;
    for (int s = t; s < NUM_HBM; s += blockDim.x) {
        pat_s[s] = pat_g[h * NUM_HBM + s];
        g_src_page[h * NUM_HBM + s] = -1;
    }
    if (t < TOPK) {
        const int p = topk_g[h * TOPK + t];
        topk_s[t] = p;
        slot_s[t] = d2h_g[h * NUM_DRAM + p];
    }
    __syncthreads();

    // pat scatter with wrapped negative index: hits refresh their slot,
    // misses (slot=-1) refresh slot NUM_HBM-1. All writes are step_f -> benign races.
    if (t < TOPK) {
        const int s = slot_s[t];
        pat_s[(s >= 0) ? s : (NUM_HBM - 1)] = step_f;
        if (s >= 0) atomicMax(&last_hit, t);   // last hit index (scatter last-wins)
    }
    __syncthreads();

    // Stable argsort via O(n^2) rank: rank(i) = #{j : pat[j]<pat[i] || (== && j<i)}
    for (int i = t; i < NUM_HBM; i += blockDim.x) {
        const float vi = pat_s[i];
        int r = 0;
        #pragma unroll 4
        for (int j = 0; j < NUM_HBM; j++) {
            const float vj = pat_s[j];   // shared broadcast (all threads same j)
            r += (vj < vi) || (vj == vi && j < i);
        }
        order_s[r] = i;
    }

    // Exclusive prefix count of misses (serial; 256 iterations is trivial)
    if (t == 0) {
        int c = 0;
        #pragma unroll 8
        for (int j = 0; j < TOPK; j++) {
            rank_s[j] = c;
            c += (slot_s[j] < 0);
        }
    }
    __syncthreads();

    // hbm scatter emulation:
    //  - miss j  -> victim order[rank_j] (distinct, never == 818 when misses>0
    //    since pat[818]=step_f excludes it from the lowest group)
    //  - hit  j  -> wrapped slot 818; duplicates resolved last-j-wins
    if (t < TOPK) {
        if (slot_s[t] < 0) {
            g_src_page[h * NUM_HBM + order_s[rank_s[t]]] = topk_s[t];
        } else if (t == last_hit) {
            g_src_page[h * NUM_HBM + (NUM_HBM - 1)] = topk_s[t];
        }
    }
}

// ---------------------------------------------------------------------------
// Kernel 2: bulk de-interleaving copy. One block per (head, hbm_slot) page.
// Page layout in source: e = row*256 + kv*128 + d (row<16, kv in {0,1}, d<128).
// k_out[h, s*16+row, d] = src[row*256 + d];  v_out[...] = src[row*256+128+d].
// All accesses are 16B (float4), 512 B coalesced segments.
// ---------------------------------------------------------------------------
__global__ void page_copy_kernel(const float* __restrict__ dram,
                                 const float* __restrict__ hbm,
                                 float*       __restrict__ kout,
                                 float*       __restrict__ vout)
{
    const int page_id = blockIdx.x;            // 0 .. H*NUM_HBM-1
    const int h = page_id / NUM_HBM;
    const int s = page_id - h * NUM_HBM;

    const int sp = g_src_page[page_id];
    const float4* __restrict__ src = (const float4*)(
        (sp >= 0) ? (dram + ((size_t)h * NUM_DRAM + (size_t)sp) * PAGE_ELEMS)
                  : (hbm  + (size_t)page_id * PAGE_ELEMS));

    float4* __restrict__ kbase =
        (float4*)(kout + ((size_t)h * SEQ_PER_HEAD + (size_t)s * PAGE_SIZE) * HEAD_DIM);
    float4* __restrict__ vbase =
        (float4*)(vout + ((size_t)h * SEQ_PER_HEAD + (size_t)s * PAGE_SIZE) * HEAD_DIM);

    // 1024 float4 per page. f: row = f>>6, kv = (f>>5)&1, dd = f&31.
    #pragma unroll 4
    for (int f = threadIdx.x; f < PAGE_ELEMS / 4; f += 256) {
        const float4 val = src[f];
        const int row = f >> 6;
        const int dd  = f & 31;
        if ((f >> 5) & 1) vbase[row * 32 + dd] = val;
        else              kbase[row * 32 + dd] = val;
    }
}

// ---------------------------------------------------------------------------
// Launch
// ---------------------------------------------------------------------------
extern "C" void kernel_launch(void* const* d_in, const int* in_sizes, int n_in,
                              void* d_out, int out_size)
{
    const float* dram = (const float*)d_in[0];   // (H, 4096, 4096) f32
    const float* hbm  = (const float*)d_in[1];   // (H, 819, 4096)  f32
    const float* pat  = (const float*)d_in[2];   // (H, 819)        f32
    const int*   d2h  = (const int*)  d_in[3];   // (H, 4096)       i32
    // d_in[4] = h2d (unused: it never affects the returned k/v caches)
    const int*   topk = (const int*)  d_in[5];   // (H, 256)        i32
    const int*   step = (const int*)  d_in[6];   // (1,)            i32

    float* kout = (float*)d_out;
    float* vout = (float*)d_out + KTOTAL;

    lru_setup_kernel<<<H, 1024>>>(pat, d2h, topk, step);
    page_copy_kernel<<<H * NUM_HBM, 256>>>(dram, hbm, kout, vout);
}

// round 3
// speedup vs baseline: 1.3477x; 1.3477x over previous
#include <cuda_runtime.h>
#include <cstdint>

// Problem constants (fixed by the reference)
#define H            8
#define NUM_DRAM     4096
#define NUM_HBM      819          // int(4096 * 0.2)
#define TOPK         256
#define PAGE_SIZE    16
#define HEAD_DIM     128
#define PAGE_ELEMS   4096         // 16 * 2 * 128
#define SEQ_PER_HEAD (NUM_HBM * PAGE_SIZE)              // 13104
#define KELEMS_HEAD  ((size_t)SEQ_PER_HEAD * HEAD_DIM)  // 1,677,312
#define KTOTAL       ((size_t)H * KELEMS_HEAD)          // 13,418,496

#define RANK_WARPS   32
#define RANK_CHUNKS  ((NUM_HBM + RANK_WARPS - 1) / RANK_WARPS)   // 26

// Scratch (device globals: allocation-free, rebuilt deterministically each call)
__device__ int   g_src_page[H * NUM_HBM];  // -1 => keep hbm page, else dram page id
__device__ float g_pat[H * NUM_HBM];       // pat after hit/wrap updates
__device__ int   g_order[H * NUM_HBM];     // stable argsort of g_pat per head
__device__ int   g_slot[H * TOPK];         // d2h[topk]

// ---------------------------------------------------------------------------
// K1: per-head gather + pat update. grid=H, block=256.
// Emulates JAX negative-index WRAPPING in scatters: idx=-1 -> slot 818.
//   slot = d2h[topk];  pat[slot>=0 ? slot : 818] = step_f
//   hbm scatter for hits targets wrapped slot 818, last hit wins.
// ---------------------------------------------------------------------------
__global__ void lru_gather_kernel(const float* __restrict__ pat_g,
                                  const int*   __restrict__ d2h_g,
                                  const int*   __restrict__ topk_g,
                                  const int*   __restrict__ step_g)
{
    __shared__ int last_hit;
    const int h = blockIdx.x;
    const int t = threadIdx.x;
    const float step_f = (float)(step_g[0] + 1);

    if (t == 0) last_hit = -1;
    for (int s = t; s < NUM_HBM; s += blockDim.x) {
        g_pat[h * NUM_HBM + s] = pat_g[h * NUM_HBM + s];
        g_src_page[h * NUM_HBM + s] = -1;
    }
    int slot = 0, page = 0;
    if (t < TOPK) {
        page = topk_g[h * TOPK + t];
        slot = d2h_g[h * NUM_DRAM + page];
        g_slot[h * TOPK + t] = slot;
    }
    __syncthreads();
    if (t < TOPK) {
        // pat scatter with wrapped negative index (all writes = step_f; races benign)
        g_pat[h * NUM_HBM + ((slot >= 0) ? slot : (NUM_HBM - 1))] = step_f;
        if (slot >= 0) atomicMax(&last_hit, t);
    }
    __syncthreads();
    // Hits' hbm scatter wraps to slot 818; last one wins. 818 is never a miss
    // victim (pat[818]==step_f excludes it from the m smallest), so no conflict.
    if (t == last_hit) {
        g_src_page[h * NUM_HBM + (NUM_HBM - 1)] = topk_g[h * TOPK + t];
    }
}

// ---------------------------------------------------------------------------
// K2: stable argsort ranks. grid=(H, 26), block=1024 (one warp per slot i).
// rank(i) = #{j : pat[j]<pat[i] || (pat[j]==pat[i] && j<i)};  order[rank]=i.
// ---------------------------------------------------------------------------
__global__ void lru_rank_kernel()
{
    __shared__ float pat_s[NUM_HBM];
    const int h    = blockIdx.x;
    const int t    = threadIdx.x;
    const int warp = t >> 5;
    const int lane = t & 31;

    for (int s = t; s < NUM_HBM; s += blockDim.x)
        pat_s[s] = g_pat[h * NUM_HBM + s];
    __syncthreads();

    const int i = blockIdx.y * RANK_WARPS + warp;
    if (i < NUM_HBM) {
        const float vi = pat_s[i];
        int r = 0;
        for (int j = lane; j < NUM_HBM; j += 32) {
            const float vj = pat_s[j];
            r += (vj < vi) || (vj == vi && j < i);
        }
        r = __reduce_add_sync(0xFFFFFFFFu, r);
        if (lane == 0) g_order[h * NUM_HBM + r] = i;
    }
}

// ---------------------------------------------------------------------------
// K3: miss prefix + victim scatter. grid=H, block=256.
// ---------------------------------------------------------------------------
__global__ void lru_scatter_kernel(const int* __restrict__ topk_g)
{
    __shared__ int slot_s[TOPK];
    __shared__ int rank_s[TOPK];
    const int h = blockIdx.x;
    const int t = threadIdx.x;

    slot_s[t] = g_slot[h * TOPK + t];
    __syncthreads();
    if (t == 0) {
        int c = 0;
        #pragma unroll 8
        for (int j = 0; j < TOPK; j++) {
            rank_s[j] = c;
            c += (slot_s[j] < 0);
        }
    }
    __syncthreads();
    if (slot_s[t] < 0) {
        const int victim = g_order[h * NUM_HBM + rank_s[t]];
        g_src_page[h * NUM_HBM + victim] = topk_g[h * TOPK + t];
    }
}

// ---------------------------------------------------------------------------
// K4: bulk de-interleaving copy. One block per (head, hbm_slot) page.
// src elem e = row*256 + kv*128 + d  ->  k/v[h, s*16+row, d].
// 16B accesses, 512B coalesced segments, streaming cache hints.
// ---------------------------------------------------------------------------
__global__ void page_copy_kernel(const float* __restrict__ dram,
                                 const float* __restrict__ hbm,
                                 float*       __restrict__ kout,
                                 float*       __restrict__ vout)
{
    const int page_id = blockIdx.x;            // 0 .. H*NUM_HBM-1
    const int h = page_id / NUM_HBM;
    const int s = page_id - h * NUM_HBM;

    const int sp = g_src_page[page_id];
    const float4* __restrict__ src = (const float4*)(
        (sp >= 0) ? (dram + ((size_t)h * NUM_DRAM + (size_t)sp) * PAGE_ELEMS)
                  : (hbm  + (size_t)page_id * PAGE_ELEMS));

    float4* __restrict__ kbase =
        (float4*)(kout + ((size_t)h * SEQ_PER_HEAD + (size_t)s * PAGE_SIZE) * HEAD_DIM);
    float4* __restrict__ vbase =
        (float4*)(vout + ((size_t)h * SEQ_PER_HEAD + (size_t)s * PAGE_SIZE) * HEAD_DIM);

    // 1024 float4 per page; 4 independent 16B ops per thread (MLP=4).
    #pragma unroll
    for (int u = 0; u < 4; u++) {
        const int f = threadIdx.x + u * 256;
        const float4 val = __ldcs(&src[f]);
        const int row = f >> 6;
        const int dd  = f & 31;
        if ((f >> 5) & 1) __stcs(&vbase[row * 32 + dd], val);
        else              __stcs(&kbase[row * 32 + dd], val);
    }
}

// ---------------------------------------------------------------------------
// Launch
// ---------------------------------------------------------------------------
extern "C" void kernel_launch(void* const* d_in, const int* in_sizes, int n_in,
                              void* d_out, int out_size)
{
    const float* dram = (const float*)d_in[0];   // (H, 4096, 4096) f32
    const float* hbm  = (const float*)d_in[1];   // (H, 819, 4096)  f32
    const float* pat  = (const float*)d_in[2];   // (H, 819)        f32
    const int*   d2h  = (const int*)  d_in[3];   // (H, 4096)       i32
    // d_in[4] = h2d (never affects the returned k/v caches)
    const int*   topk = (const int*)  d_in[5];   // (H, 256)        i32
    const int*   step = (const int*)  d_in[6];   // (1,)            i32

    float* kout = (float*)d_out;
    float* vout = (float*)d_out + KTOTAL;

    lru_gather_kernel<<<H, 256>>>(pat, d2h, topk, step);
    lru_rank_kernel<<<dim3(H, RANK_CHUNKS), RANK_WARPS * 32>>>();
    lru_scatter_kernel<<<H, TOPK>>>(topk);
    page_copy_kernel<<<H * NUM_HBM, 256>>>(dram, hbm, kout, vout);
}

// round 4
// speedup vs baseline: 1.5578x; 1.1559x over previous
#include <cuda_runtime.h>
#include <cstdint>

// Problem constants (fixed by the reference)
#define H            8
#define NUM_DRAM     4096
#define NUM_HBM      819          // int(4096 * 0.2)
#define TOPK         256
#define PAGE_SIZE    16
#define HEAD_DIM     128
#define PAGE_ELEMS   4096         // 16 * 2 * 128
#define SEQ_PER_HEAD (NUM_HBM * PAGE_SIZE)              // 13104
#define KELEMS_HEAD  ((size_t)SEQ_PER_HEAD * HEAD_DIM)  // 1,677,312
#define KTOTAL       ((size_t)H * KELEMS_HEAD)          // 13,418,496

#define SLOTS_PER_BLK 32
#define RANK_CHUNKS   ((NUM_HBM + SLOTS_PER_BLK - 1) / SLOTS_PER_BLK)  // 26

// Scratch: for each (head, hbm_slot), the DRAM page to pull in (-1 => keep hbm page)
__device__ int g_src_page[H * NUM_HBM];

// ---------------------------------------------------------------------------
// Fused setup kernel. grid=(H, 26), block=1024 (one warp per owned slot).
//
// Emulates the reference exactly, including JAX's negative-index WRAPPING in
// scatters (idx=-1 -> slot 818, applied before mode='drop'):
//   slot = d2h[topk]
//   pat[slot>=0 ? slot : 818] = step_f
//   stable rank(i) over pat;  slot i is a victim iff rank(i) < n_miss,
//   receiving the page of the rank(i)-th miss (inverse of order[r] scatter).
//   Hits scatter to wrapped slot 818, last hit wins (818 is never a victim
//   since pat[818]==step_f puts its rank above any possible n_miss).
//
// Every block redundantly recomputes the per-head control state (cheap) so
// no cross-block dependency / extra kernel is needed.
// ---------------------------------------------------------------------------
__global__ void lru_setup_kernel(const float* __restrict__ pat_g,
                                 const int*   __restrict__ d2h_g,
                                 const int*   __restrict__ topk_g,
                                 const int*   __restrict__ step_g)
{
    __shared__ float pat_s[NUM_HBM];
    __shared__ int   topk_s[TOPK];
    __shared__ int   slot_s[TOPK];
    __shared__ int   miss_page[TOPK];
    __shared__ int   warp_pre[TOPK / 32];   // per-warp miss counts -> exclusive scan
    __shared__ int   n_miss_s, last_hit_s, last_hit_page_s;

    const int h    = blockIdx.x;
    const int t    = threadIdx.x;
    const int warp = t >> 5;
    const int lane = t & 31;
    const float step_f = (float)(step_g[0] + 1);

    if (t == 0) { last_hit_s = -1; last_hit_page_s = -1; }
    for (int s = t; s < NUM_HBM; s += blockDim.x)
        pat_s[s] = pat_g[h * NUM_HBM + s];

    bool miss = false;
    int  wpre = 0;
    if (t < TOPK) {
        const int p = topk_g[h * TOPK + t];
        topk_s[t] = p;
        const int slot = d2h_g[h * NUM_DRAM + p];
        slot_s[t] = slot;
        miss = (slot < 0);
        const unsigned m = __ballot_sync(0xFFFFFFFFu, miss);
        wpre = __popc(m & ((1u << lane) - 1u));
        if (lane == 0) warp_pre[warp] = __popc(m);
        if (!miss) atomicMax(&last_hit_s, t);
    }
    __syncthreads();

    // pat scatter with wrapped negative index (all writes = step_f; races benign)
    if (t < TOPK) {
        const int slot = slot_s[t];
        pat_s[(slot >= 0) ? slot : (NUM_HBM - 1)] = step_f;
    }
    // exclusive scan of the 8 warp miss-counts
    if (t == 0) {
        int c = 0;
        #pragma unroll
        for (int w = 0; w < TOPK / 32; w++) { const int x = warp_pre[w]; warp_pre[w] = c; c += x; }
        n_miss_s = c;
    }
    __syncthreads();

    if (t < TOPK) {
        if (miss) miss_page[warp_pre[warp] + wpre] = topk_s[t];
        if (t == last_hit_s) last_hit_page_s = topk_s[t];
    }
    __syncthreads();

    // One warp per slot: stable rank(i) = #{j: pat[j]<pat[i] || (== && j<i)}
    const int i = blockIdx.y * SLOTS_PER_BLK + warp;
    if (i < NUM_HBM) {
        const float vi = pat_s[i];
        int r = 0;
        for (int j = lane; j < NUM_HBM; j += 32) {
            const float vj = pat_s[j];
            r += (vj < vi) || (vj == vi && j < i);
        }
        r = __reduce_add_sync(0xFFFFFFFFu, r);
        if (lane == 0) {
            int sp = (r < n_miss_s) ? miss_page[r] : -1;
            if (i == NUM_HBM - 1 && last_hit_page_s >= 0) sp = last_hit_page_s;
            g_src_page[h * NUM_HBM + i] = sp;
        }
    }
}

// ---------------------------------------------------------------------------
// Bulk de-interleaving copy. One block per (head, hbm_slot) page.
// src elem e = row*256 + kv*128 + d  ->  k/v[h, s*16+row, d].
// Plain LDG/STG.128, 512B coalesced segments (streaming hints measured slower).
// ---------------------------------------------------------------------------
__global__ void page_copy_kernel(const float* __restrict__ dram,
                                 const float* __restrict__ hbm,
                                 float*       __restrict__ kout,
                                 float*       __restrict__ vout)
{
    const int page_id = blockIdx.x;            // 0 .. H*NUM_HBM-1
    const int h = page_id / NUM_HBM;
    const int s = page_id - h * NUM_HBM;

    const int sp = g_src_page[page_id];
    const float4* __restrict__ src = (const float4*)(
        (sp >= 0) ? (dram + ((size_t)h * NUM_DRAM + (size_t)sp) * PAGE_ELEMS)
                  : (hbm  + (size_t)page_id * PAGE_ELEMS));

    float4* __restrict__ kbase =
        (float4*)(kout + ((size_t)h * SEQ_PER_HEAD + (size_t)s * PAGE_SIZE) * HEAD_DIM);
    float4* __restrict__ vbase =
        (float4*)(vout + ((size_t)h * SEQ_PER_HEAD + (size_t)s * PAGE_SIZE) * HEAD_DIM);

    // 1024 float4 per page; 4 independent 16B ops per thread (MLP=4).
    #pragma unroll 4
    for (int f = threadIdx.x; f < PAGE_ELEMS / 4; f += 256) {
        const float4 val = src[f];
        const int row = f >> 6;
        const int dd  = f & 31;
        if ((f >> 5) & 1) vbase[row * 32 + dd] = val;
        else              kbase[row * 32 + dd] = val;
    }
}

// ---------------------------------------------------------------------------
// Launch
// ---------------------------------------------------------------------------
extern "C" void kernel_launch(void* const* d_in, const int* in_sizes, int n_in,
                              void* d_out, int out_size)
{
    const float* dram = (const float*)d_in[0];   // (H, 4096, 4096) f32
    const float* hbm  = (const float*)d_in[1];   // (H, 819, 4096)  f32
    const float* pat  = (const float*)d_in[2];   // (H, 819)        f32
    const int*   d2h  = (const int*)  d_in[3];   // (H, 4096)       i32
    // d_in[4] = h2d (never affects the returned k/v caches)
    const int*   topk = (const int*)  d_in[5];   // (H, 256)        i32
    const int*   step = (const int*)  d_in[6];   // (1,)            i32

    float* kout = (float*)d_out;
    float* vout = (float*)d_out + KTOTAL;

    lru_setup_kernel<<<dim3(H, RANK_CHUNKS), 1024>>>(pat, d2h, topk, step);
    page_copy_kernel<<<H * NUM_HBM, 256>>>(dram, hbm, kout, vout);
}